// round 9
// baseline (speedup 1.0000x reference)
#include <cuda_runtime.h>

#define B_    16
#define C_    64
#define WH    65536                 // 256*256
#define NELEM (B_ * C_ * WH)        // 67,108,864 elements
#define EPS_  0.001f

#define NBLK_ST     4096            // stats chunks: plane*4 + sub, 16384 floats
#define NBLK_NORM   16384           // 1024 float4 per block

// ---- scratch (device globals; plain stores, rewritten every launch) ----
__device__ float g_Sp[NBLK_ST];              // partial sum  [(b*64+c)*4 + sub]
__device__ float g_Qp[NBLK_ST];              // partial sumsq
__device__ int   g_cntc[B_ * 4];             // masked count [b*4 + sub]
__device__ float g_inv[C_];                  // 1/sqrt(var+eps)
__device__ int   g_done;                     // stats last-block counter (self-reset)
__device__ volatile int g_ready;             // g_inv published flag
__device__ int   g_norm_done;                // norm last-block counter (self-reset)

__device__ __forceinline__ void acc_f32x2(unsigned long long& s,
                                          unsigned long long& q,
                                          unsigned long long v) {
    asm("add.rn.f32x2 %0, %0, %1;" : "+l"(s) : "l"(v));
    asm("fma.rn.f32x2 %0, %1, %1, %0;" : "+l"(q) : "l"(v));
}
__device__ __forceinline__ float2 unpack2(unsigned long long v) {
    float2 r;
    asm("mov.b64 {%0, %1}, %2;" : "=f"(r.x), "=f"(r.y) : "l"(v));
    return r;
}

// ---- stats: S_c = sum x, Q_c = sum x^2 over everything (unmasked pixels are
// exactly 0 in every channel => no mask needed for sums). Counts from
// channel-0 nonzeros. Trigger-at-top: PDL lets norm CTAs backfill retiring
// SMs during the last stats wave; correctness is gated by g_ready, NOT by
// the trigger. Last finishing block finalizes inline and publishes g_ready. ----
__global__ void __launch_bounds__(256) k_stats(const float* __restrict__ x) {
    const int tid = threadIdx.x;
    const int blk = blockIdx.x;
    if (tid == 0) cudaTriggerProgrammaticLaunchCompletion();
    int plane = blk >> 2;
    int sub   = blk & 3;
    bool docnt = ((plane & (C_ - 1)) == 0);
    __shared__ float ss[8], sq[8];
    __shared__ int   scn[8];
    __shared__ int   sh_last;
    __shared__ int   sh_n[B_];
    __shared__ int   sh_nmax;

    float s, q;
    int cnt = 0;
    if (!docnt) {
        const ulonglong2* base =
            (const ulonglong2*)(x + (size_t)plane * WH + sub * 16384);
        unsigned long long sA = 0, sB = 0, qA = 0, qB = 0;
        #pragma unroll
        for (int k = 0; k < 16; k++) {
            ulonglong2 v = __ldg(base + k * 256 + tid);
            acc_f32x2(sA, qA, v.x);
            acc_f32x2(sB, qB, v.y);
        }
        float2 a = unpack2(sA), b2 = unpack2(sB);
        float2 c2 = unpack2(qA), d2 = unpack2(qB);
        s = (a.x + a.y) + (b2.x + b2.y);
        q = (c2.x + c2.y) + (d2.x + d2.y);
    } else {                         // 64/4096 chunks: count own nonzeros too
        const float4* base = (const float4*)(x + (size_t)plane * WH + sub * 16384);
        float s0 = 0.0f, s1 = 0.0f, q0 = 0.0f, q1 = 0.0f;
        #pragma unroll
        for (int k = 0; k < 16; k++) {
            float4 v = __ldg(base + k * 256 + tid);
            s0 += v.x; q0 = fmaf(v.x, v.x, q0);
            s1 += v.y; q1 = fmaf(v.y, v.y, q1);
            s0 += v.z; q0 = fmaf(v.z, v.z, q0);
            s1 += v.w; q1 = fmaf(v.w, v.w, q1);
            cnt += (int)(v.x != 0.0f) + (int)(v.y != 0.0f)
                 + (int)(v.z != 0.0f) + (int)(v.w != 0.0f);
        }
        s = s0 + s1; q = q0 + q1;
        cnt = __reduce_add_sync(0xFFFFFFFFu, cnt);
    }
    #pragma unroll
    for (int o = 16; o; o >>= 1) {
        s += __shfl_xor_sync(0xFFFFFFFFu, s, o);
        q += __shfl_xor_sync(0xFFFFFFFFu, q, o);
    }
    int w = tid >> 5;
    if ((tid & 31) == 0) { ss[w] = s; sq[w] = q; scn[w] = cnt; }
    __syncthreads();
    if (tid == 0) {
        float S = 0.0f, Q = 0.0f;
        #pragma unroll
        for (int i = 0; i < 8; i++) { S += ss[i]; Q += sq[i]; }
        g_Sp[blk] = S;
        g_Qp[blk] = Q;
        if (docnt) {
            int t = 0;
            #pragma unroll
            for (int i = 0; i < 8; i++) t += scn[i];
            g_cntc[(plane >> 6) * 4 + sub] = t;
        }
        __threadfence();                         // release partials
        int old = atomicAdd(&g_done, 1);
        sh_last = (old == NBLK_ST - 1) ? 1 : 0;
        if (sh_last) g_done = 0;                 // reset for next graph replay
    }
    __syncthreads();
    if (!sh_last) return;

    // ---- inline finalize, exactly one block, partials L2-hot ----
    __threadfence();                             // acquire
    if (tid < B_) {
        int4 c4 = *(const int4*)&g_cntc[tid << 2];
        sh_n[tid] = (c4.x + c4.y) + (c4.z + c4.w);
    }
    __syncthreads();
    if (tid == 0) {
        int nmax = 0;
        #pragma unroll
        for (int b = 0; b < B_; b++) nmax = max(nmax, sh_n[b]);
        sh_nmax = nmax;
    }
    __syncthreads();
    int nmax = sh_nmax;
    int c = tid >> 2, j = tid & 3;               // 4 threads per channel
    float S = 0.0f, Q = 0.0f;
    #pragma unroll
    for (int b4 = 0; b4 < 4; b4++) {             // this thread: batches j*4+b4
        int b = j * 4 + b4;
        int pbase = (b * C_ + c) << 2;
        float4 s4 = *(const float4*)&g_Sp[pbase];
        float4 q4 = *(const float4*)&g_Qp[pbase];
        float x00 = __ldg(&x[(size_t)(b * C_ + c) << 16]);
        float pad = (float)(nmax - sh_n[b]);
        S += (s4.x + s4.y) + (s4.z + s4.w);
        Q += (q4.x + q4.y) + (q4.z + q4.w);
        S = fmaf(pad, x00, S);
        Q = fmaf(pad * x00, x00, Q);
    }
    S += __shfl_xor_sync(0xFFFFFFFFu, S, 1, 4);
    S += __shfl_xor_sync(0xFFFFFFFFu, S, 2, 4);
    Q += __shfl_xor_sync(0xFFFFFFFFu, Q, 1, 4);
    Q += __shfl_xor_sync(0xFFFFFFFFu, Q, 2, 4);
    if (j == 0) {
        float total = (float)(B_ * nmax);
        float mean  = S / total;
        float var   = Q / total - mean * mean;
        g_inv[c] = rsqrtf(var + EPS_);
    }
    __syncthreads();
    if (tid == 0) { __threadfence(); g_ready = 1; }   // publish g_inv
}

// ---- normalize: out = x * inv[c] unconditionally. One chunk per block,
// reverse order. PDL: prefetch x (read-only) while stats finishes, then wait
// on g_ready (the REAL dependency), then scale + store. ----
__global__ void __launch_bounds__(256) k_norm(const float* __restrict__ x,
                                              float* __restrict__ out) {
    const int tid = threadIdx.x;
    int blk = (NBLK_NORM - 1) - blockIdx.x;
    size_t base4 = (size_t)blk * 1024;               // float4 index of block base
    int c = (int)(base4 >> 14) & (C_ - 1);           // block lies in one plane
    float4 v0 = __ldcs((const float4*)x + base4 +   0 + tid);
    float4 v1 = __ldcs((const float4*)x + base4 + 256 + tid);
    float4 v2 = __ldcs((const float4*)x + base4 + 512 + tid);
    float4 v3 = __ldcs((const float4*)x + base4 + 768 + tid);
    cudaGridDependencySynchronize();                 // all stats CTAs triggered
    if (tid == 0) { while (g_ready == 0) __nanosleep(64); }
    __syncthreads();
    __threadfence();                                 // acquire g_inv
    float inv = __ldg(&g_inv[c]);
    float4 o;
    o.x = v0.x * inv; o.y = v0.y * inv; o.z = v0.z * inv; o.w = v0.w * inv;
    __stcs((float4*)out + base4 +   0 + tid, o);
    o.x = v1.x * inv; o.y = v1.y * inv; o.z = v1.z * inv; o.w = v1.w * inv;
    __stcs((float4*)out + base4 + 256 + tid, o);
    o.x = v2.x * inv; o.y = v2.y * inv; o.z = v2.z * inv; o.w = v2.w * inv;
    __stcs((float4*)out + base4 + 512 + tid, o);
    o.x = v3.x * inv; o.y = v3.y * inv; o.z = v3.z * inv; o.w = v3.w * inv;
    __stcs((float4*)out + base4 + 768 + tid, o);
    // last norm block resets sync state for the next graph replay
    __syncthreads();
    if (tid == 0) {
        int old = atomicAdd(&g_norm_done, 1);
        if (old == NBLK_NORM - 1) { g_ready = 0; g_norm_done = 0; }
    }
}

extern "C" void kernel_launch(void* const* d_in, const int* in_sizes, int n_in,
                              void* d_out, int out_size) {
    const float* x = (const float*)d_in[0];
    float* out = (float*)d_out;
    k_stats<<<NBLK_ST, 256>>>(x);

    cudaLaunchConfig_t cfg = {};
    cfg.gridDim  = dim3(NBLK_NORM, 1, 1);
    cfg.blockDim = dim3(256, 1, 1);
    cfg.dynamicSmemBytes = 0;
    cfg.stream = 0;                              // same (captured) stream
    cudaLaunchAttribute attr[1];
    attr[0].id = cudaLaunchAttributeProgrammaticStreamSerialization;
    attr[0].val.programmaticStreamSerializationAllowed = 1;
    cfg.attrs = attr;
    cfg.numAttrs = 1;
    cudaLaunchKernelEx(&cfg, k_norm, x, out);
}

// round 10
// speedup vs baseline: 1.0394x; 1.0394x over previous
#include <cuda_runtime.h>

#define B_    16
#define C_    64
#define WH    65536                 // 256*256
#define NELEM (B_ * C_ * WH)        // 67,108,864 elements
#define EPS_  0.001f

#define NBLK_ST     4096            // stats chunks: plane*4 + sub, 16384 floats
#define NBLK_NORM   16384           // 1024 float4 per block

// ---- scratch (device globals; plain stores, rewritten every launch) ----
__device__ float g_Sp[NBLK_ST];              // partial sum  [(b*64+c)*4 + sub]
__device__ float g_Qp[NBLK_ST];              // partial sumsq
__device__ int   g_cntc[B_ * 4];             // masked count [b*4 + sub]
__device__ float g_inv[C_];                  // 1/sqrt(var+eps)
__device__ int   g_done;                     // last-block-done counter (self-reset)

__device__ __forceinline__ void acc_f32x2(unsigned long long& s,
                                          unsigned long long& q,
                                          unsigned long long v) {
    asm("add.rn.f32x2 %0, %0, %1;" : "+l"(s) : "l"(v));
    asm("fma.rn.f32x2 %0, %1, %1, %0;" : "+l"(q) : "l"(v));
}
__device__ __forceinline__ float2 unpack2(unsigned long long v) {
    float2 r;
    asm("mov.b64 {%0, %1}, %2;" : "=f"(r.x), "=f"(r.y) : "l"(v));
    return r;
}

// ---- stats: S_c = sum x, Q_c = sum x^2 over everything (unmasked pixels are
// exactly 0 in every channel => no mask needed for sums). Counts come from
// channel-0 nonzeros only. Explicit 4-deep load batching keeps >=4 LDGs in
// flight per thread; packed f32x2 keeps the FMA pipe under the DRAM budget.
// Last finishing block runs the finalize inline (partials are L2-hot). ----
__global__ void __launch_bounds__(256) k_stats(const float* __restrict__ x) {
    const int tid = threadIdx.x;
    const int blk = blockIdx.x;
    int plane = blk >> 2;
    int sub   = blk & 3;
    bool docnt = ((plane & (C_ - 1)) == 0);
    __shared__ float ss[8], sq[8];
    __shared__ int   scn[8];
    __shared__ int   sh_last;
    __shared__ int   sh_n[B_];
    __shared__ int   sh_nmax;

    float s, q;
    int cnt = 0;
    if (!docnt) {
        const ulonglong2* base =
            (const ulonglong2*)(x + (size_t)plane * WH + sub * 16384);
        unsigned long long sA = 0, sB = 0, qA = 0, qB = 0;
        #pragma unroll
        for (int k = 0; k < 4; k++) {
            ulonglong2 v0 = __ldg(base + (k * 4 + 0) * 256 + tid);  // 4 loads
            ulonglong2 v1 = __ldg(base + (k * 4 + 1) * 256 + tid);  // in flight
            ulonglong2 v2 = __ldg(base + (k * 4 + 2) * 256 + tid);
            ulonglong2 v3 = __ldg(base + (k * 4 + 3) * 256 + tid);
            acc_f32x2(sA, qA, v0.x); acc_f32x2(sB, qB, v0.y);
            acc_f32x2(sA, qA, v1.x); acc_f32x2(sB, qB, v1.y);
            acc_f32x2(sA, qA, v2.x); acc_f32x2(sB, qB, v2.y);
            acc_f32x2(sA, qA, v3.x); acc_f32x2(sB, qB, v3.y);
        }
        float2 a = unpack2(sA), b2 = unpack2(sB);
        float2 c2 = unpack2(qA), d2 = unpack2(qB);
        s = (a.x + a.y) + (b2.x + b2.y);
        q = (c2.x + c2.y) + (d2.x + d2.y);
    } else {                         // 64/4096 chunks: count own nonzeros too
        const float4* base = (const float4*)(x + (size_t)plane * WH + sub * 16384);
        float s0 = 0.0f, s1 = 0.0f, q0 = 0.0f, q1 = 0.0f;
        #pragma unroll
        for (int k = 0; k < 16; k++) {
            float4 v = __ldg(base + k * 256 + tid);
            s0 += v.x; q0 = fmaf(v.x, v.x, q0);
            s1 += v.y; q1 = fmaf(v.y, v.y, q1);
            s0 += v.z; q0 = fmaf(v.z, v.z, q0);
            s1 += v.w; q1 = fmaf(v.w, v.w, q1);
            cnt += (int)(v.x != 0.0f) + (int)(v.y != 0.0f)
                 + (int)(v.z != 0.0f) + (int)(v.w != 0.0f);
        }
        s = s0 + s1; q = q0 + q1;
        cnt = __reduce_add_sync(0xFFFFFFFFu, cnt);
    }
    #pragma unroll
    for (int o = 16; o; o >>= 1) {
        s += __shfl_xor_sync(0xFFFFFFFFu, s, o);
        q += __shfl_xor_sync(0xFFFFFFFFu, q, o);
    }
    int w = tid >> 5;
    if ((tid & 31) == 0) { ss[w] = s; sq[w] = q; scn[w] = cnt; }
    __syncthreads();
    if (tid == 0) {
        float S = 0.0f, Q = 0.0f;
        #pragma unroll
        for (int i = 0; i < 8; i++) { S += ss[i]; Q += sq[i]; }
        g_Sp[blk] = S;
        g_Qp[blk] = Q;
        if (docnt) {
            int t = 0;
            #pragma unroll
            for (int i = 0; i < 8; i++) t += scn[i];
            g_cntc[(plane >> 6) * 4 + sub] = t;
        }
        __threadfence();                         // release partials
        int old = atomicAdd(&g_done, 1);
        sh_last = (old == NBLK_ST - 1) ? 1 : 0;
        if (sh_last) g_done = 0;                 // reset for next graph replay
    }
    __syncthreads();
    if (!sh_last) return;

    // ---- inline finalize, exactly one block, partials L2-hot ----
    __threadfence();                             // acquire
    if (tid < B_) {
        int4 c4 = *(const int4*)&g_cntc[tid << 2];
        sh_n[tid] = (c4.x + c4.y) + (c4.z + c4.w);
    }
    __syncthreads();
    if (tid == 0) {
        int nmax = 0;
        #pragma unroll
        for (int b = 0; b < B_; b++) nmax = max(nmax, sh_n[b]);
        sh_nmax = nmax;
    }
    __syncthreads();
    int nmax = sh_nmax;
    int c = tid >> 2, j = tid & 3;               // 4 threads per channel
    float S = 0.0f, Q = 0.0f;
    #pragma unroll
    for (int b4 = 0; b4 < 4; b4++) {             // this thread: batches j*4+b4
        int b = j * 4 + b4;
        int pbase = (b * C_ + c) << 2;
        float4 s4 = *(const float4*)&g_Sp[pbase];
        float4 q4 = *(const float4*)&g_Qp[pbase];
        float x00 = __ldg(&x[(size_t)(b * C_ + c) << 16]);
        float pad = (float)(nmax - sh_n[b]);
        S += (s4.x + s4.y) + (s4.z + s4.w);
        Q += (q4.x + q4.y) + (q4.z + q4.w);
        S = fmaf(pad, x00, S);
        Q = fmaf(pad * x00, x00, Q);
    }
    S += __shfl_xor_sync(0xFFFFFFFFu, S, 1, 4);
    S += __shfl_xor_sync(0xFFFFFFFFu, S, 2, 4);
    Q += __shfl_xor_sync(0xFFFFFFFFu, Q, 1, 4);
    Q += __shfl_xor_sync(0xFFFFFFFFu, Q, 2, 4);
    if (j == 0) {
        float total = (float)(B_ * nmax);
        float mean  = S / total;
        float var   = Q / total - mean * mean;
        g_inv[c] = rsqrtf(var + EPS_);
    }
}

// ---- normalize: out = x * inv[c] unconditionally (unmasked x are exact 0;
// (0,0) pad override is also x00*inv). One chunk per block (max chip-level
// MLP), reverse address order to catch the L2 tail left by stats. ----
__global__ void __launch_bounds__(256) k_norm(const float* __restrict__ x,
                                              float* __restrict__ out) {
    const int tid = threadIdx.x;
    int blk = (NBLK_NORM - 1) - blockIdx.x;
    size_t base4 = (size_t)blk * 1024;               // float4 index of block base
    int c = (int)(base4 >> 14) & (C_ - 1);           // block lies in one plane
    float inv = __ldg(&g_inv[c]);
    float4 v0 = __ldcs((const float4*)x + base4 +   0 + tid);
    float4 v1 = __ldcs((const float4*)x + base4 + 256 + tid);
    float4 v2 = __ldcs((const float4*)x + base4 + 512 + tid);
    float4 v3 = __ldcs((const float4*)x + base4 + 768 + tid);
    float4 o;
    o.x = v0.x * inv; o.y = v0.y * inv; o.z = v0.z * inv; o.w = v0.w * inv;
    __stcs((float4*)out + base4 +   0 + tid, o);
    o.x = v1.x * inv; o.y = v1.y * inv; o.z = v1.z * inv; o.w = v1.w * inv;
    __stcs((float4*)out + base4 + 256 + tid, o);
    o.x = v2.x * inv; o.y = v2.y * inv; o.z = v2.z * inv; o.w = v2.w * inv;
    __stcs((float4*)out + base4 + 512 + tid, o);
    o.x = v3.x * inv; o.y = v3.y * inv; o.z = v3.z * inv; o.w = v3.w * inv;
    __stcs((float4*)out + base4 + 768 + tid, o);
}

extern "C" void kernel_launch(void* const* d_in, const int* in_sizes, int n_in,
                              void* d_out, int out_size) {
    const float* x = (const float*)d_in[0];
    float* out = (float*)d_out;
    k_stats<<<NBLK_ST, 256>>>(x);
    k_norm <<<NBLK_NORM, 256>>>(x, out);
}

// round 11
// speedup vs baseline: 1.0490x; 1.0092x over previous
#include <cuda_runtime.h>

#define B_    16
#define C_    64
#define WH    65536                 // 256*256
#define NELEM (B_ * C_ * WH)        // 67,108,864 elements
#define EPS_  0.001f

#define NBLK_ST     4096            // stats chunks: plane*4 + sub, 16384 floats
#define NBLK_NORM   8192            // 2048 float4 (8 KB) per block

// ---- scratch (device globals; plain stores, rewritten every launch) ----
__device__ float g_Sp[NBLK_ST];              // partial sum  [(b*64+c)*4 + sub]
__device__ float g_Qp[NBLK_ST];              // partial sumsq
__device__ int   g_cntc[B_ * 4];             // masked count [b*4 + sub]
__device__ float g_inv[C_];                  // 1/sqrt(var+eps)
__device__ int   g_done;                     // last-block-done counter (self-reset)

__device__ __forceinline__ void acc_f32x2(unsigned long long& s,
                                          unsigned long long& q,
                                          unsigned long long v) {
    asm("add.rn.f32x2 %0, %0, %1;" : "+l"(s) : "l"(v));
    asm("fma.rn.f32x2 %0, %1, %1, %0;" : "+l"(q) : "l"(v));
}
__device__ __forceinline__ float2 unpack2(unsigned long long v) {
    float2 r;
    asm("mov.b64 {%0, %1}, %2;" : "=f"(r.x), "=f"(r.y) : "l"(v));
    return r;
}

// ---- stats: S_c = sum x, Q_c = sum x^2 over everything (unmasked pixels are
// exactly 0 in every channel => no mask needed for sums). Counts come from
// channel-0 nonzeros only. Packed f32x2 keeps the FMA pipe under the DRAM
// budget. Last finishing block runs the finalize inline (partials L2-hot). ----
__global__ void __launch_bounds__(256) k_stats(const float* __restrict__ x) {
    const int tid = threadIdx.x;
    const int blk = blockIdx.x;
    int plane = blk >> 2;
    int sub   = blk & 3;
    bool docnt = ((plane & (C_ - 1)) == 0);
    __shared__ float ss[8], sq[8];
    __shared__ int   scn[8];
    __shared__ int   sh_last;
    __shared__ int   sh_n[B_];
    __shared__ int   sh_nmax;

    float s, q;
    int cnt = 0;
    if (!docnt) {
        const ulonglong2* base =
            (const ulonglong2*)(x + (size_t)plane * WH + sub * 16384);
        unsigned long long sA = 0, sB = 0, qA = 0, qB = 0;
        #pragma unroll
        for (int k = 0; k < 16; k++) {
            ulonglong2 v = __ldg(base + k * 256 + tid);
            acc_f32x2(sA, qA, v.x);
            acc_f32x2(sB, qB, v.y);
        }
        float2 a = unpack2(sA), b2 = unpack2(sB);
        float2 c2 = unpack2(qA), d2 = unpack2(qB);
        s = (a.x + a.y) + (b2.x + b2.y);
        q = (c2.x + c2.y) + (d2.x + d2.y);
    } else {                         // 64/4096 chunks: count own nonzeros too
        const float4* base = (const float4*)(x + (size_t)plane * WH + sub * 16384);
        float s0 = 0.0f, s1 = 0.0f, q0 = 0.0f, q1 = 0.0f;
        #pragma unroll
        for (int k = 0; k < 16; k++) {
            float4 v = __ldg(base + k * 256 + tid);
            s0 += v.x; q0 = fmaf(v.x, v.x, q0);
            s1 += v.y; q1 = fmaf(v.y, v.y, q1);
            s0 += v.z; q0 = fmaf(v.z, v.z, q0);
            s1 += v.w; q1 = fmaf(v.w, v.w, q1);
            cnt += (int)(v.x != 0.0f) + (int)(v.y != 0.0f)
                 + (int)(v.z != 0.0f) + (int)(v.w != 0.0f);
        }
        s = s0 + s1; q = q0 + q1;
        cnt = __reduce_add_sync(0xFFFFFFFFu, cnt);
    }
    #pragma unroll
    for (int o = 16; o; o >>= 1) {
        s += __shfl_xor_sync(0xFFFFFFFFu, s, o);
        q += __shfl_xor_sync(0xFFFFFFFFu, q, o);
    }
    int w = tid >> 5;
    if ((tid & 31) == 0) { ss[w] = s; sq[w] = q; scn[w] = cnt; }
    __syncthreads();
    if (tid == 0) {
        float S = 0.0f, Q = 0.0f;
        #pragma unroll
        for (int i = 0; i < 8; i++) { S += ss[i]; Q += sq[i]; }
        g_Sp[blk] = S;
        g_Qp[blk] = Q;
        if (docnt) {
            int t = 0;
            #pragma unroll
            for (int i = 0; i < 8; i++) t += scn[i];
            g_cntc[(plane >> 6) * 4 + sub] = t;
        }
        __threadfence();                         // release partials
        int old = atomicAdd(&g_done, 1);
        sh_last = (old == NBLK_ST - 1) ? 1 : 0;
        if (sh_last) g_done = 0;                 // reset for next graph replay
    }
    __syncthreads();
    if (!sh_last) return;

    // ---- inline finalize, exactly one block, partials L2-hot ----
    __threadfence();                             // acquire
    if (tid < B_) {
        int4 c4 = *(const int4*)&g_cntc[tid << 2];
        sh_n[tid] = (c4.x + c4.y) + (c4.z + c4.w);
    }
    __syncthreads();
    if (tid == 0) {
        int nmax = 0;
        #pragma unroll
        for (int b = 0; b < B_; b++) nmax = max(nmax, sh_n[b]);
        sh_nmax = nmax;
    }
    __syncthreads();
    int nmax = sh_nmax;
    int c = tid >> 2, j = tid & 3;               // 4 threads per channel
    float S = 0.0f, Q = 0.0f;
    #pragma unroll
    for (int b4 = 0; b4 < 4; b4++) {             // this thread: batches j*4+b4
        int b = j * 4 + b4;
        int pbase = (b * C_ + c) << 2;
        float4 s4 = *(const float4*)&g_Sp[pbase];
        float4 q4 = *(const float4*)&g_Qp[pbase];
        float x00 = __ldg(&x[(size_t)(b * C_ + c) << 16]);
        float pad = (float)(nmax - sh_n[b]);
        S += (s4.x + s4.y) + (s4.z + s4.w);
        Q += (q4.x + q4.y) + (q4.z + q4.w);
        S = fmaf(pad, x00, S);
        Q = fmaf(pad * x00, x00, Q);
    }
    S += __shfl_xor_sync(0xFFFFFFFFu, S, 1, 4);
    S += __shfl_xor_sync(0xFFFFFFFFu, S, 2, 4);
    Q += __shfl_xor_sync(0xFFFFFFFFu, Q, 1, 4);
    Q += __shfl_xor_sync(0xFFFFFFFFu, Q, 2, 4);
    if (j == 0) {
        float total = (float)(B_ * nmax);
        float mean  = S / total;
        float var   = Q / total - mean * mean;
        g_inv[c] = rsqrtf(var + EPS_);
    }
}

// ---- normalize: out = x * inv[c] unconditionally (unmasked x are exact 0;
// (0,0) pad override is also x00*inv). 8 KB per block, ALL 8 loads front-
// batched before any store (long read burst, then long write burst -> fewer
// DRAM turnarounds). Reverse address order to catch the L2 tail. 8 KB chunk
// spans 2048 float4 within one plane (WH*4 = 256 KB per plane, 32 chunks). ----
__global__ void __launch_bounds__(256) k_norm(const float* __restrict__ x,
                                              float* __restrict__ out) {
    const int tid = threadIdx.x;
    int blk = (NBLK_NORM - 1) - blockIdx.x;
    size_t base4 = (size_t)blk * 2048;               // float4 index of block base
    int c = (int)(base4 >> 14) & (C_ - 1);           // block lies in one plane
    float inv = __ldg(&g_inv[c]);
    float4 v[8];
    #pragma unroll
    for (int k = 0; k < 8; k++)                      // 8 reads in flight
        v[k] = __ldcs((const float4*)x + base4 + k * 256 + tid);
    #pragma unroll
    for (int k = 0; k < 8; k++) {
        float4 o;
        o.x = v[k].x * inv; o.y = v[k].y * inv;
        o.z = v[k].z * inv; o.w = v[k].w * inv;
        __stcs((float4*)out + base4 + k * 256 + tid, o);
    }
}

extern "C" void kernel_launch(void* const* d_in, const int* in_sizes, int n_in,
                              void* d_out, int out_size) {
    const float* x = (const float*)d_in[0];
    float* out = (float*)d_out;
    k_stats<<<NBLK_ST, 256>>>(x);
    k_norm <<<NBLK_NORM, 256>>>(x, out);
}

// round 12
// speedup vs baseline: 1.0525x; 1.0033x over previous
#include <cuda_runtime.h>

#define B_    16
#define C_    64
#define WH    65536                 // 256*256
#define NELEM (B_ * C_ * WH)        // 67,108,864 elements
#define EPS_  0.001f

#define NBLK_ST     1024            // one plane (256 KB) per block — single wave
#define NBLK_NORM   8192            // 2048 float4 (8 KB) per block

// ---- scratch (device globals; plain stores, rewritten every launch) ----
__device__ float g_Sp[NBLK_ST];              // per-plane sum   [b*64+c]
__device__ float g_Qp[NBLK_ST];              // per-plane sumsq
__device__ int   g_cnt[B_];                  // per-batch masked count
__device__ float g_inv[C_];                  // 1/sqrt(var+eps)
__device__ int   g_done;                     // last-block-done counter (self-reset)

__device__ __forceinline__ void acc_f32x2(unsigned long long& s,
                                          unsigned long long& q,
                                          unsigned long long v) {
    asm("add.rn.f32x2 %0, %0, %1;" : "+l"(s) : "l"(v));
    asm("fma.rn.f32x2 %0, %1, %1, %0;" : "+l"(q) : "l"(v));
}
__device__ __forceinline__ float2 unpack2(unsigned long long v) {
    float2 r;
    asm("mov.b64 {%0, %1}, %2;" : "=f"(r.x), "=f"(r.y) : "l"(v));
    return r;
}

// ---- stats: S_c = sum x, Q_c = sum x^2 over everything (unmasked pixels are
// exactly 0 in every channel => no mask needed for sums). One plane per block,
// 1024 blocks = ONE wave (all co-resident on 148 SMs): no wave quantization,
// one reduction tail per 256 KB. The 16 channel-0 blocks also count their own
// nonzeros (keep=0 => x[b,0,p]==0 exactly). Last finishing block finalizes. ----
__global__ void __launch_bounds__(256) k_stats(const float* __restrict__ x) {
    const int tid = threadIdx.x;
    const int plane = blockIdx.x;                // b*64 + c
    bool docnt = ((plane & (C_ - 1)) == 0);
    __shared__ float ss[8], sq[8];
    __shared__ int   scn[8];
    __shared__ int   sh_last;
    __shared__ int   sh_n[B_];
    __shared__ int   sh_nmax;

    const ulonglong2* base = (const ulonglong2*)(x + (size_t)plane * WH);
    unsigned long long sA = 0, sB = 0, qA = 0, qB = 0;
    int cnt = 0;
    if (!docnt) {
        #pragma unroll 8
        for (int k = 0; k < 64; k++) {
            ulonglong2 v = __ldg(base + k * 256 + tid);
            acc_f32x2(sA, qA, v.x);
            acc_f32x2(sB, qB, v.y);
        }
    } else {                                     // 16 / 1024 blocks: also count
        const float4* fbase = (const float4*)base;
        #pragma unroll 8
        for (int k = 0; k < 64; k++) {
            float4 v = __ldg(fbase + k * 256 + tid);
            unsigned long long p0, p1;
            asm("mov.b64 %0, {%1, %2};" : "=l"(p0) : "f"(v.x), "f"(v.y));
            asm("mov.b64 %0, {%1, %2};" : "=l"(p1) : "f"(v.z), "f"(v.w));
            acc_f32x2(sA, qA, p0);
            acc_f32x2(sB, qB, p1);
            cnt += (int)(v.x != 0.0f) + (int)(v.y != 0.0f)
                 + (int)(v.z != 0.0f) + (int)(v.w != 0.0f);
        }
        cnt = __reduce_add_sync(0xFFFFFFFFu, cnt);
    }
    float2 a = unpack2(sA), b2 = unpack2(sB);
    float2 c2 = unpack2(qA), d2 = unpack2(qB);
    float s = (a.x + a.y) + (b2.x + b2.y);
    float q = (c2.x + c2.y) + (d2.x + d2.y);
    #pragma unroll
    for (int o = 16; o; o >>= 1) {
        s += __shfl_xor_sync(0xFFFFFFFFu, s, o);
        q += __shfl_xor_sync(0xFFFFFFFFu, q, o);
    }
    int w = tid >> 5;
    if ((tid & 31) == 0) { ss[w] = s; sq[w] = q; scn[w] = cnt; }
    __syncthreads();
    if (tid == 0) {
        float S = 0.0f, Q = 0.0f;
        #pragma unroll
        for (int i = 0; i < 8; i++) { S += ss[i]; Q += sq[i]; }
        g_Sp[plane] = S;
        g_Qp[plane] = Q;
        if (docnt) {
            int t = 0;
            #pragma unroll
            for (int i = 0; i < 8; i++) t += scn[i];
            g_cnt[plane >> 6] = t;
        }
        __threadfence();                         // release partials
        int old = atomicAdd(&g_done, 1);
        sh_last = (old == NBLK_ST - 1) ? 1 : 0;
        if (sh_last) g_done = 0;                 // reset for next graph replay
    }
    __syncthreads();
    if (!sh_last) return;

    // ---- inline finalize, exactly one block, partials L2-hot ----
    __threadfence();                             // acquire
    if (tid < B_) sh_n[tid] = g_cnt[tid];
    __syncthreads();
    if (tid == 0) {
        int nmax = 0;
        #pragma unroll
        for (int b = 0; b < B_; b++) nmax = max(nmax, sh_n[b]);
        sh_nmax = nmax;
    }
    __syncthreads();
    int nmax = sh_nmax;
    int c = tid >> 2, j = tid & 3;               // 4 threads per channel
    float S = 0.0f, Q = 0.0f;
    #pragma unroll
    for (int b4 = 0; b4 < 4; b4++) {             // this thread: batches j*4+b4
        int b = j * 4 + b4;
        int pl = b * C_ + c;
        float Sp  = g_Sp[pl];
        float Qp  = g_Qp[pl];
        float x00 = __ldg(&x[(size_t)pl << 16]);
        float pad = (float)(nmax - sh_n[b]);
        S += fmaf(pad, x00, Sp);
        Q += fmaf(pad * x00, x00, Qp);
    }
    S += __shfl_xor_sync(0xFFFFFFFFu, S, 1, 4);
    S += __shfl_xor_sync(0xFFFFFFFFu, S, 2, 4);
    Q += __shfl_xor_sync(0xFFFFFFFFu, Q, 1, 4);
    Q += __shfl_xor_sync(0xFFFFFFFFu, Q, 2, 4);
    if (j == 0) {
        float total = (float)(B_ * nmax);
        float mean  = S / total;
        float var   = Q / total - mean * mean;
        g_inv[c] = rsqrtf(var + EPS_);
    }
}

// ---- normalize: out = x * inv[c] unconditionally (unmasked x are exact 0;
// (0,0) pad override is also x00*inv). 8 KB per block, ALL 8 loads front-
// batched (long read burst then long write burst -> fewer DRAM turnarounds).
// Reverse address order to catch the L2 tail left by stats. ----
__global__ void __launch_bounds__(256) k_norm(const float* __restrict__ x,
                                              float* __restrict__ out) {
    const int tid = threadIdx.x;
    int blk = (NBLK_NORM - 1) - blockIdx.x;
    size_t base4 = (size_t)blk * 2048;               // float4 index of block base
    int c = (int)(base4 >> 14) & (C_ - 1);           // block lies in one plane
    float inv = __ldg(&g_inv[c]);
    float4 v[8];
    #pragma unroll
    for (int k = 0; k < 8; k++)                      // 8 reads in flight
        v[k] = __ldcs((const float4*)x + base4 + k * 256 + tid);
    #pragma unroll
    for (int k = 0; k < 8; k++) {
        float4 o;
        o.x = v[k].x * inv; o.y = v[k].y * inv;
        o.z = v[k].z * inv; o.w = v[k].w * inv;
        __stcs((float4*)out + base4 + k * 256 + tid, o);
    }
}

extern "C" void kernel_launch(void* const* d_in, const int* in_sizes, int n_in,
                              void* d_out, int out_size) {
    const float* x = (const float*)d_in[0];
    float* out = (float*)d_out;
    k_stats<<<NBLK_ST, 256>>>(x);
    k_norm <<<NBLK_NORM, 256>>>(x, out);
}